// round 1
// baseline (speedup 1.0000x reference)
#include <cuda_runtime.h>

// BezierToImageLayer: sparse Gaussian splat formulation.
// out[b,i,j] = min(1, sum_{l,n} exp(-(i/60 - X_{b,l,n})^2/a) * exp(-(j/60 - Y_{b,l,n})^2/a))
// with a = 2e-4  =>  each sample only touches an 8x8 pixel window (tail < 2.2e-10).

#define BDIM     256
#define NWARPS   8
#define WPIX     60
#define STRIDE   68           // 68 % 32 == 4 -> 8x4 window access hits 32 distinct banks
#define NSAMP    30
#define NCURVE   160
#define ACC_WORDS (NWARPS * WPIX * STRIDE)   // 32640 floats = 130560 B

__global__ __launch_bounds__(BDIM, 1)
void bezier_splat_kernel(const float* __restrict__ x, float* __restrict__ out)
{
    extern __shared__ float acc[];   // [NWARPS][WPIX][STRIDE], per-warp private

    const int b    = blockIdx.x;
    const int tid  = threadIdx.x;
    const int w    = tid >> 5;
    const int lane = tid & 31;

    // ---- zero private accumulators ----
    for (int i = tid; i < ACC_WORDS; i += BDIM) acc[i] = 0.0f;
    __syncthreads();

    float* __restrict__ my = acc + w * (WPIX * STRIDE);

    // lane ownership: absolute row residue mod 8, absolute col residue mod 4
    const int ra = lane >> 2;   // 0..7
    const int ca = lane & 3;    // 0..3

    // ---- per-lane Bezier basis (lane == sample index n) ----
    const int   n  = (lane < NSAMP) ? lane : (NSAMP - 1);
    const float u  = (float)n * (1.0f / (float)NSAMP);
    const float t  = 2.0f*u*u*u - 3.0f*u*u + 2.0f*u;
    const float t2 = t * t;
    const float t3 = t2 * t;
    const float b0 = t3;
    const float b1 = 3.0f * (t2 - t3);
    const float b2 = 3.0f * (t3 - 2.0f*t2 + t);
    const float tb = 1.0f - t;
    const float b3 = tb * tb * tb;

    const float inv60 = 1.0f / 60.0f;
    const float negK  = -5000.0f;       // -1/ALPHA

    const float* __restrict__ xb = x + (size_t)b * (NCURVE * 8);

    // each warp handles curves l = w + 8*c  (disjoint cover of 0..159)
    for (int c = 0; c < NCURVE / NWARPS; ++c) {
        const int l = w + NWARPS * c;
        const float* ct = xb + l * 8;   // [x0,y0,x1,y1,x2,y2,x3,y3] broadcast loads

        // this lane's sample point on the curve
        const float Xn = b0*ct[0] + b1*ct[2] + b2*ct[4] + b3*ct[6];
        const float Yn = b0*ct[1] + b1*ct[3] + b2*ct[5] + b3*ct[7];

        #pragma unroll 10
        for (int s = 0; s < NSAMP; ++s) {
            const float X = __shfl_sync(0xffffffffu, Xn, s);
            const float Y = __shfl_sync(0xffffffffu, Yn, s);

            // 8x8 window origin (X,Y guaranteed in [0,1] -> trunc == floor)
            int i0 = (int)(X * 60.0f) - 3; i0 = max(i0, 0); i0 = min(i0, WPIX - 8);
            int j0 = (int)(Y * 60.0f) - 3; j0 = max(j0, 0); j0 = min(j0, WPIX - 8);

            // lane's absolute cells inside the window (fixed residues -> no lane collisions)
            const int i  = i0 + ((ra - i0) & 7);
            const int j1 = j0 + ((ca - j0) & 3);   // second col is j1 + 4

            const float dx  = fmaf((float)i,  inv60, -X);
            const float dy1 = fmaf((float)j1, inv60, -Y);
            const float dy2 = dy1 + 4.0f * inv60;

            const float gx = __expf(dx  * dx  * negK);
            const float g1 = __expf(dy1 * dy1 * negK) * gx;
            const float g2 = __expf(dy2 * dy2 * negK) * gx;

            float* __restrict__ p = my + i * STRIDE + j1;
            p[0] += g1;
            p[4] += g2;
        }
    }
    __syncthreads();

    // ---- reduce the 8 private copies, clamp, store ----
    float* __restrict__ ob = out + (size_t)b * (WPIX * WPIX);
    for (int idx = tid; idx < WPIX * WPIX; idx += BDIM) {
        const int i = idx / WPIX;
        const int j = idx - i * WPIX;
        float s = 0.0f;
        #pragma unroll
        for (int ww = 0; ww < NWARPS; ++ww)
            s += acc[ww * (WPIX * STRIDE) + i * STRIDE + j];
        ob[idx] = fminf(s, 1.0f);
    }
}

extern "C" void kernel_launch(void* const* d_in, const int* in_sizes, int n_in,
                              void* d_out, int out_size)
{
    (void)in_sizes; (void)n_in; (void)out_size;
    const float* x  = (const float*)d_in[0];
    float* out      = (float*)d_out;

    static_assert(ACC_WORDS * 4 == 130560, "smem size");
    cudaFuncSetAttribute(bezier_splat_kernel,
                         cudaFuncAttributeMaxDynamicSharedMemorySize,
                         ACC_WORDS * (int)sizeof(float));

    bezier_splat_kernel<<<256, BDIM, ACC_WORDS * (int)sizeof(float)>>>(x, out);
}

// round 2
// speedup vs baseline: 1.2652x; 1.2652x over previous
#include <cuda_runtime.h>

// BezierToImageLayer — sparse Gaussian splat, round 2.
// out[b,i,j] = min(1, sum_{l,n} exp(-5000*((i/60-X)^2)) * exp(-5000*((j/60-Y)^2)))
// Window truncated to 8x8 px (tail < 2.2e-10).
//
// R2 changes vs R1 (91.3us, issue 65%, occ 12.5%):
//  - 128-thread CTAs, 4 private smem copies (65.3KB) -> 3 CTAs/SM = 12 warps/SM
//  - grid 1024 (4 curve-chunks per batch) -> no 2-wave imbalance; partials in
//    __device__ scratch, combined + clamped by a small second kernel (deterministic)
//  - pixel-unit coordinates + prefolded ex2 constant: fewer instrs/sample

#define BDIM     128
#define NWARPS   4            // warps per CTA
#define NSPLIT   4            // CTAs per batch
#define WPIX     60
#define STRIDE   68           // ≡ 4 (mod 32): (4i+j) distinct over 8x4 window -> conflict-free
#define NSAMP    30
#define NCURVE   160
#define CPT      (NCURVE / NSPLIT)          // 40 curves per task
#define CPW      (CPT / NWARPS)             // 10 curves per warp
#define ACC_WORDS (NWARPS * WPIX * STRIDE)  // 16320 floats = 65280 B

#define NBATCH   256
#define IMG      (WPIX * WPIX)

__device__ float g_scratch[NBATCH * NSPLIT * IMG];   // 14.7 MB partials

__device__ __forceinline__ float ex2f(float a) {
    float r; asm("ex2.approx.f32 %0, %1;" : "=f"(r) : "f"(a)); return r;
}

__global__ __launch_bounds__(BDIM, 3)
void bezier_splat_kernel(const float* __restrict__ x)
{
    extern __shared__ float acc[];   // [NWARPS][WPIX][STRIDE], per-warp private

    const int task = blockIdx.x;          // 0..1023
    const int b    = task >> 2;
    const int part = task & (NSPLIT - 1);
    const int tid  = threadIdx.x;
    const int w    = tid >> 5;
    const int lane = tid & 31;

    // ---- zero private accumulators (vectorized) ----
    float4* az = (float4*)acc;
    #pragma unroll
    for (int i = tid; i < ACC_WORDS / 4; i += BDIM)
        az[i] = make_float4(0.f, 0.f, 0.f, 0.f);
    __syncthreads();

    float* __restrict__ my = acc + w * (WPIX * STRIDE);

    // lane ownership: absolute row residue mod 8, absolute col residue mod 4
    const int ra = lane >> 2;   // 0..7
    const int ca = lane & 3;    // 0..3

    // ---- per-lane Bezier basis (lane == sample index n), pre-scaled to pixels ----
    const int   n  = (lane < NSAMP) ? lane : (NSAMP - 1);
    const float u  = (float)n * (1.0f / (float)NSAMP);
    const float t  = 2.0f*u*u*u - 3.0f*u*u + 2.0f*u;
    const float t2 = t * t;
    const float t3 = t2 * t;
    const float tb = 1.0f - t;
    // basis * 60 (pixel units)
    const float b0 = 60.0f * t3;
    const float b1 = 180.0f * (t2 - t3);
    const float b2 = 180.0f * (t3 - 2.0f*t2 + t);
    const float b3 = 60.0f * tb * tb * tb;

    // exp(-5000*(d_px/60)^2) = exp2(C2 * d_px^2)
    const float C2 = -2.0037431123457827f;   // -(5000/3600)*log2(e)

    const float* __restrict__ xb = x + ((size_t)b * NCURVE + part * CPT) * 8;

    for (int c = 0; c < CPW; ++c) {
        const int l = w + NWARPS * c;       // 0..39 within this chunk
        const float* ct = xb + l * 8;       // broadcast loads

        // this lane's sample point on the curve, in pixel units
        const float Xn = b0*ct[0] + b1*ct[2] + b2*ct[4] + b3*ct[6];
        const float Yn = b0*ct[1] + b1*ct[3] + b2*ct[5] + b3*ct[7];

        #pragma unroll 10
        for (int s = 0; s < NSAMP; ++s) {
            const float Xp = __shfl_sync(0xffffffffu, Xn, s);
            const float Yp = __shfl_sync(0xffffffffu, Yn, s);

            // 8x8 window origin (Xp,Yp in [0,60) -> trunc == floor)
            int i0 = (int)Xp - 3; i0 = max(i0, 0); i0 = min(i0, WPIX - 8);
            int j0 = (int)Yp - 3; j0 = max(j0, 0); j0 = min(j0, WPIX - 8);

            // lane's absolute cells (fixed residues -> no lane collisions)
            const int i  = i0 + ((ra - i0) & 7);
            const int j1 = j0 + ((ca - j0) & 3);   // second col is j1 + 4

            const float dx  = (float)i  - Xp;
            const float dy1 = (float)j1 - Yp;
            const float dy2 = dy1 + 4.0f;

            const float gx = ex2f(dx  * dx  * C2);
            const float g1 = ex2f(dy1 * dy1 * C2) * gx;
            const float g2 = ex2f(dy2 * dy2 * C2) * gx;

            float* __restrict__ p = my + i * STRIDE + j1;
            p[0] += g1;
            p[4] += g2;
        }
    }
    __syncthreads();

    // ---- reduce 4 private copies -> scratch partial for this task ----
    float* __restrict__ sp = g_scratch + (size_t)task * IMG;
    for (int idx = tid; idx < IMG; idx += BDIM) {
        const int i = idx / WPIX;
        const int j = idx - i * WPIX;
        const int o = i * STRIDE + j;
        float s = acc[o]
                + acc[1 * (WPIX * STRIDE) + o]
                + acc[2 * (WPIX * STRIDE) + o]
                + acc[3 * (WPIX * STRIDE) + o];
        sp[idx] = s;
    }
}

__global__ __launch_bounds__(256)
void bezier_combine_kernel(float* __restrict__ out)
{
    const int idx = blockIdx.x * 256 + threadIdx.x;   // over 256*3600
    if (idx >= NBATCH * IMG) return;
    const int b = idx / IMG;
    const int c = idx - b * IMG;
    const float* sp = g_scratch + ((size_t)b * NSPLIT) * IMG + c;
    float s = sp[0] + sp[IMG] + sp[2 * IMG] + sp[3 * IMG];
    out[idx] = fminf(s, 1.0f);
}

extern "C" void kernel_launch(void* const* d_in, const int* in_sizes, int n_in,
                              void* d_out, int out_size)
{
    (void)in_sizes; (void)n_in; (void)out_size;
    const float* x = (const float*)d_in[0];
    float* out     = (float*)d_out;

    cudaFuncSetAttribute(bezier_splat_kernel,
                         cudaFuncAttributeMaxDynamicSharedMemorySize,
                         ACC_WORDS * (int)sizeof(float));

    bezier_splat_kernel<<<NBATCH * NSPLIT, BDIM, ACC_WORDS * (int)sizeof(float)>>>(x);
    bezier_combine_kernel<<<(NBATCH * IMG + 255) / 256, 256>>>(out);
}

// round 3
// speedup vs baseline: 1.3093x; 1.0349x over previous
#include <cuda_runtime.h>

// BezierToImageLayer — sparse Gaussian splat, round 3.
// out[b,i,j] = min(1, sum_{l,n} exp(-5000*((i/60-X)^2 + ... )))  window 8x8 px.
//
// R3 vs R2 (72.2us = 65 splat + 7.2 combine):
//  - padded 67x68 per-warp accumulator: X,Y in [0,1) guaranteed (convex comb of
//    uniform[0,1) ctrl pts) -> window origin in [-3,56] -> NO clamps (-4 instr/sample)
//  - combine kernel: float4 x 4-partial loads, 4 px/thread (MLP to hide DRAM lat)

#define BDIM     128
#define NWARPS   4            // warps per CTA
#define NSPLIT   4            // CTAs per batch
#define WPIX     60
#define AROWS    67           // rows -3..63
#define STRIDE   68           // cols -3..64 fit; 68 % 32 == 4 -> 8x4 window conflict-free
#define PAD      3
#define NSAMP    30
#define NCURVE   160
#define CPT      (NCURVE / NSPLIT)          // 40 curves per task
#define CPW      (CPT / NWARPS)             // 10 curves per warp
#define COPY_W   (AROWS * STRIDE)           // 4556 floats per warp copy
#define ACC_WORDS (NWARPS * COPY_W)         // 18224 floats = 72896 B

#define NBATCH   256
#define IMG      (WPIX * WPIX)

__device__ float g_scratch[NBATCH * NSPLIT * IMG];   // 14.7 MB partials

__device__ __forceinline__ float ex2f(float a) {
    float r; asm("ex2.approx.f32 %0, %1;" : "=f"(r) : "f"(a)); return r;
}

__global__ __launch_bounds__(BDIM, 3)
void bezier_splat_kernel(const float* __restrict__ x)
{
    extern __shared__ float acc[];   // [NWARPS][AROWS][STRIDE], per-warp private

    const int task = blockIdx.x;          // 0..1023
    const int b    = task >> 2;
    const int part = task & (NSPLIT - 1);
    const int tid  = threadIdx.x;
    const int w    = tid >> 5;
    const int lane = tid & 31;

    // ---- zero private accumulators (vectorized) ----
    float4* az = (float4*)acc;
    for (int i = tid; i < ACC_WORDS / 4; i += BDIM)
        az[i] = make_float4(0.f, 0.f, 0.f, 0.f);
    __syncthreads();

    // origin shifted so row/col -3 is legal
    float* __restrict__ my = acc + w * COPY_W + PAD * STRIDE + PAD;

    // lane ownership: absolute row residue mod 8, absolute col residue mod 4
    const int ra = lane >> 2;   // 0..7
    const int ca = lane & 3;    // 0..3

    // ---- per-lane Bezier basis (lane == sample index n), pre-scaled to pixels ----
    const int   n  = (lane < NSAMP) ? lane : (NSAMP - 1);
    const float u  = (float)n * (1.0f / (float)NSAMP);
    const float t  = 2.0f*u*u*u - 3.0f*u*u + 2.0f*u;
    const float t2 = t * t;
    const float t3 = t2 * t;
    const float tb = 1.0f - t;
    const float b0 = 60.0f * t3;
    const float b1 = 180.0f * (t2 - t3);
    const float b2 = 180.0f * (t3 - 2.0f*t2 + t);
    const float b3 = 60.0f * tb * tb * tb;

    // exp(-5000*(d_px/60)^2) = exp2(C2 * d_px^2)
    const float C2 = -2.0037431123457827f;   // -(5000/3600)*log2(e)

    const float* __restrict__ xb = x + ((size_t)b * NCURVE + part * CPT) * 8;

    for (int c = 0; c < CPW; ++c) {
        const int l = w + NWARPS * c;       // 0..39 within this chunk
        const float* ct = xb + l * 8;       // broadcast loads

        // this lane's sample point on the curve, pixel units, in [0,60)
        const float Xn = b0*ct[0] + b1*ct[2] + b2*ct[4] + b3*ct[6];
        const float Yn = b0*ct[1] + b1*ct[3] + b2*ct[5] + b3*ct[7];

        #pragma unroll 10
        for (int s = 0; s < NSAMP; ++s) {
            const float Xp = __shfl_sync(0xffffffffu, Xn, s);
            const float Yp = __shfl_sync(0xffffffffu, Yn, s);

            // window origin (Xp,Yp in [0,60) -> trunc == floor; no clamps needed)
            const int mi = (int)Xp;
            const int mj = (int)Yp;

            // lane's absolute cells: i in [mi-3, mi+4], i ≡ ra (mod 8); same for cols mod 4
            const int i  = mi - 3 + ((ra + 3 - mi) & 7);
            const int j1 = mj - 3 + ((ca + 3 - mj) & 3);   // second col is j1 + 4

            const float dx  = (float)i  - Xp;
            const float dy1 = (float)j1 - Yp;
            const float dy2 = dy1 + 4.0f;

            const float gx = ex2f(dx  * dx  * C2);
            const float g1 = ex2f(dy1 * dy1 * C2) * gx;
            const float g2 = ex2f(dy2 * dy2 * C2) * gx;

            float* __restrict__ p = my + i * STRIDE + j1;
            p[0] += g1;
            p[4] += g2;
        }
    }
    __syncthreads();

    // ---- reduce 4 private copies -> scratch partial for this task ----
    float* __restrict__ sp = g_scratch + (size_t)task * IMG;
    const float* __restrict__ a0 = acc + PAD * STRIDE + PAD;
    for (int idx = tid; idx < IMG; idx += BDIM) {
        const int i = idx / WPIX;
        const int j = idx - i * WPIX;
        const int o = i * STRIDE + j;
        float s = a0[o]
                + a0[1 * COPY_W + o]
                + a0[2 * COPY_W + o]
                + a0[3 * COPY_W + o];
        sp[idx] = s;
    }
}

__global__ __launch_bounds__(256)
void bezier_combine_kernel(float* __restrict__ out)
{
    // 4 pixels per thread, float4 loads for MLP
    const int gid = blockIdx.x * 256 + threadIdx.x;     // over 921600/4 = 230400
    if (gid >= NBATCH * IMG / 4) return;
    const int p4 = gid * 4;
    const int b  = p4 / IMG;
    const int c  = p4 - b * IMG;                        // multiple of 4 within batch
    const float4* s0 = (const float4*)(g_scratch + ((size_t)b * NSPLIT    ) * IMG + c);
    const float4* s1 = (const float4*)(g_scratch + ((size_t)b * NSPLIT + 1) * IMG + c);
    const float4* s2 = (const float4*)(g_scratch + ((size_t)b * NSPLIT + 2) * IMG + c);
    const float4* s3 = (const float4*)(g_scratch + ((size_t)b * NSPLIT + 3) * IMG + c);
    const float4 v0 = *s0, v1 = *s1, v2 = *s2, v3 = *s3;
    float4 r;
    r.x = fminf(v0.x + v1.x + v2.x + v3.x, 1.0f);
    r.y = fminf(v0.y + v1.y + v2.y + v3.y, 1.0f);
    r.z = fminf(v0.z + v1.z + v2.z + v3.z, 1.0f);
    r.w = fminf(v0.w + v1.w + v2.w + v3.w, 1.0f);
    *(float4*)(out + p4) = r;
}

extern "C" void kernel_launch(void* const* d_in, const int* in_sizes, int n_in,
                              void* d_out, int out_size)
{
    (void)in_sizes; (void)n_in; (void)out_size;
    const float* x = (const float*)d_in[0];
    float* out     = (float*)d_out;

    cudaFuncSetAttribute(bezier_splat_kernel,
                         cudaFuncAttributeMaxDynamicSharedMemorySize,
                         ACC_WORDS * (int)sizeof(float));

    bezier_splat_kernel<<<NBATCH * NSPLIT, BDIM, ACC_WORDS * (int)sizeof(float)>>>(x);
    bezier_combine_kernel<<<(NBATCH * IMG / 4 + 255) / 256, 256>>>(out);
}